// round 1
// baseline (speedup 1.0000x reference)
#include <cuda_runtime.h>
#include <cuda_bf16.h>
#include <mma.h>

using namespace nvcuda;
using bf16 = __nv_bfloat16;

#define H 1024
#define BATCH 8
#define SEQ 2048
#define ROWS (BATCH * SEQ)   // 16384

// ---------------- scratch (static device globals; no allocation) ----------------
__device__ float g_xqn_f32[(size_t)ROWS * H];          // 64 MB
__device__ bf16  g_xqn_bf [(size_t)ROWS * H];          // 32 MB
__device__ bf16  g_kr     [(size_t)ROWS * H];          // 32 MB
__device__ bf16  g_vr     [(size_t)ROWS * H];          // 32 MB
__device__ bf16  g_qr     [(size_t)ROWS * H];          // 32 MB (pre-scaled by 1/sqrt(H))
__device__ bf16  g_E      [(size_t)BATCH * SEQ * SEQ]; // 64 MB (exp(scores), bf16)
__device__ bf16  g_qWb    [(size_t)H * H];             // 2 MB
__device__ float g_gate   [H];
__device__ float g_Zpart  [BATCH * 256];
__device__ float g_Zinv   [BATCH];

__device__ __forceinline__ float sigmoidf(float x) { return 1.f / (1.f + expf(-x)); }

__device__ __forceinline__ void store_bf4(bf16* p, float a, float b, float c, float d) {
    __nv_bfloat162 lo = __floats2bfloat162_rn(a, b);
    __nv_bfloat162 hi = __floats2bfloat162_rn(c, d);
    uint2 u;
    u.x = *reinterpret_cast<unsigned*>(&lo);
    u.y = *reinterpret_cast<unsigned*>(&hi);
    *reinterpret_cast<uint2*>(p) = u;
}

// ---------------- small prep kernels ----------------
__global__ void cvt_qw_kernel(const float* __restrict__ qW) {
    int i = blockIdx.x * blockDim.x + threadIdx.x;
    if (i < H * H) g_qWb[i] = __float2bfloat16(qW[i]);
}

// gate[h] = sigmoid(vp . v1W[h] + v1b[h]) * tanh(vp . v2W[h] + v2b[h]),  vp = sigmoid(v_prime)
__global__ void gate_kernel(const float* __restrict__ v_prime,
                            const float* __restrict__ v1W, const float* __restrict__ v1b,
                            const float* __restrict__ v2W, const float* __restrict__ v2b) {
    int warp = (blockIdx.x * blockDim.x + threadIdx.x) >> 5;
    int lane = threadIdx.x & 31;
    if (warp >= H) return;
    float s1 = 0.f, s2 = 0.f;
    for (int i = lane; i < H; i += 32) {
        float vp = sigmoidf(v_prime[i]);
        s1 += vp * v1W[warp * H + i];
        s2 += vp * v2W[warp * H + i];
    }
#pragma unroll
    for (int o = 16; o; o >>= 1) {
        s1 += __shfl_xor_sync(0xffffffffu, s1, o);
        s2 += __shfl_xor_sync(0xffffffffu, s2, o);
    }
    if (lane == 0)
        g_gate[warp] = sigmoidf(s1 + v1b[warp]) * tanhf(s2 + v2b[warp]);
}

// ---------------- fused dual LayerNorm + elementwise ----------------
__global__ void ln_kernel(const float* __restrict__ x,
                          const float* __restrict__ qn_w, const float* __restrict__ qn_b,
                          const float* __restrict__ kvn_w, const float* __restrict__ kvn_b,
                          const float* __restrict__ k_prime) {
    int row = blockIdx.x;
    int tid = threadIdx.x;
    size_t base = (size_t)row * H;
    float4 v = *reinterpret_cast<const float4*>(x + base + tid * 4);
    float s  = v.x + v.y + v.z + v.w;
    float ss = v.x * v.x + v.y * v.y + v.z * v.z + v.w * v.w;
#pragma unroll
    for (int o = 16; o; o >>= 1) {
        s  += __shfl_xor_sync(0xffffffffu, s, o);
        ss += __shfl_xor_sync(0xffffffffu, ss, o);
    }
    __shared__ float shs[8], shss[8];
    int w = tid >> 5, l = tid & 31;
    if (l == 0) { shs[w] = s; shss[w] = ss; }
    __syncthreads();
    float ts = 0.f, tss = 0.f;
#pragma unroll
    for (int i = 0; i < 8; i++) { ts += shs[i]; tss += shss[i]; }
    float mean = ts * (1.f / H);
    float var  = tss * (1.f / H) - mean * mean;
    float rstd = rsqrtf(var + 1e-5f);

    int j = tid * 4;
    float4 qw  = *reinterpret_cast<const float4*>(qn_w + j);
    float4 qb4 = *reinterpret_cast<const float4*>(qn_b + j);
    float4 kw  = *reinterpret_cast<const float4*>(kvn_w + j);
    float4 kb4 = *reinterpret_cast<const float4*>(kvn_b + j);
    float4 kp  = *reinterpret_cast<const float4*>(k_prime + j);
    float4 gt  = *reinterpret_cast<const float4*>(g_gate + j);

    float xh0 = (v.x - mean) * rstd, xh1 = (v.y - mean) * rstd;
    float xh2 = (v.z - mean) * rstd, xh3 = (v.w - mean) * rstd;

    float xq0 = xh0 * qw.x + qb4.x, xq1 = xh1 * qw.y + qb4.y;
    float xq2 = xh2 * qw.z + qb4.z, xq3 = xh3 * qw.w + qb4.w;
    float xk0 = xh0 * kw.x + kb4.x, xk1 = xh1 * kw.y + kb4.y;
    float xk2 = xh2 * kw.z + kb4.z, xk3 = xh3 * kw.w + kb4.w;

    *reinterpret_cast<float4*>(g_xqn_f32 + base + j) = make_float4(xq0, xq1, xq2, xq3);
    store_bf4(g_xqn_bf + base + j, xq0, xq1, xq2, xq3);
    store_bf4(g_kr + base + j, xk0 * sigmoidf(kp.x), xk1 * sigmoidf(kp.y),
                               xk2 * sigmoidf(kp.z), xk3 * sigmoidf(kp.w));
    store_bf4(g_vr + base + j, xk0 * gt.x, xk1 * gt.y, xk2 * gt.z, xk3 * gt.w);
}

// ---------------- generic 128x128 bf16 wmma GEMM with fused epilogues ----------------
// EK = 0: qr   = (xqn_bf @ qWb^T + qb) * sigmoid(q_prime) * (1/32)   -> g_qr (bf16)
// EK = 1: E    = exp(qr @ kr^T)                                       -> g_E (bf16) + tile partial sums
// EK = 2: out  = (E @ vr) * Zinv[b] + xqn_f32                         -> d_out (fp32)
template<int EK>
__global__ void gemm_kernel(const float* __restrict__ e0, const float* __restrict__ e1,
                            float* __restrict__ outf) {
    constexpr bool B_KN = (EK == 2);                  // B stored [K,N] row-major (vr)
    constexpr int  Kdim = (EK == 2) ? 2048 : 1024;
    constexpr int  lda  = (EK == 2) ? 2048 : 1024;
    constexpr int  ldb  = 1024;                        // qWb/kr: [N,K] ld=1024; vr: [K,N] ld=1024
    constexpr int  BM = 128, BN = 128, BK = 32;

    __shared__ __align__(32) bf16 As[BM * 48];
    __shared__ __align__(32) bf16 Bs[BN * 48];        // also fits 32*144 for B_KN
    __shared__ __align__(32) float epi_buf[8][256];
    __shared__ float red[8];

    int tid = threadIdx.x;
    int bz  = blockIdx.z;
    int m0  = blockIdx.y * BM, n0 = blockIdx.x * BN;
    int w = tid >> 5, lane = tid & 31;
    int wm = w >> 2, wn = w & 3;

    const bf16* A;
    const bf16* B;
    if (EK == 0)      { A = g_xqn_bf; B = g_qWb; }
    else if (EK == 1) { A = g_qr + (size_t)bz * SEQ * H;  B = g_kr + (size_t)bz * SEQ * H; }
    else              { A = g_E  + (size_t)bz * SEQ * SEQ; B = g_vr + (size_t)bz * SEQ * H; }

    wmma::fragment<wmma::accumulator, 16, 16, 16, float> acc[4][2];
#pragma unroll
    for (int i = 0; i < 4; i++)
#pragma unroll
        for (int j = 0; j < 2; j++) wmma::fill_fragment(acc[i][j], 0.f);

    for (int k0 = 0; k0 < Kdim; k0 += BK) {
        // load A tile [128 x 32] row-major, ld 48
        for (int i = tid; i < BM * 8; i += 256) {
            int r = i >> 3, c = (i & 7) << 2;
            *reinterpret_cast<uint2*>(&As[r * 48 + c]) =
                *reinterpret_cast<const uint2*>(&A[(size_t)(m0 + r) * lda + k0 + c]);
        }
        if (B_KN) {
            // B [K,N] row-major -> Bs[k][n], ld 144
            for (int i = tid; i < BK * 32; i += 256) {
                int r = i >> 5, c = (i & 31) << 2;
                *reinterpret_cast<uint2*>(&Bs[r * 144 + c]) =
                    *reinterpret_cast<const uint2*>(&B[(size_t)(k0 + r) * ldb + n0 + c]);
            }
        } else {
            // B [N,K] row-major -> Bs[n][k], ld 48 (col-major for wmma)
            for (int i = tid; i < BN * 8; i += 256) {
                int r = i >> 3, c = (i & 7) << 2;
                *reinterpret_cast<uint2*>(&Bs[r * 48 + c]) =
                    *reinterpret_cast<const uint2*>(&B[(size_t)(n0 + r) * ldb + k0 + c]);
            }
        }
        __syncthreads();

#pragma unroll
        for (int kk = 0; kk < BK; kk += 16) {
            wmma::fragment<wmma::matrix_a, 16, 16, 16, bf16, wmma::row_major> fa[4];
#pragma unroll
            for (int i = 0; i < 4; i++)
                wmma::load_matrix_sync(fa[i], &As[(wm * 64 + i * 16) * 48 + kk], 48);
            if (B_KN) {
                wmma::fragment<wmma::matrix_b, 16, 16, 16, bf16, wmma::row_major> fb[2];
#pragma unroll
                for (int j = 0; j < 2; j++)
                    wmma::load_matrix_sync(fb[j], &Bs[kk * 144 + wn * 32 + j * 16], 144);
#pragma unroll
                for (int i = 0; i < 4; i++)
#pragma unroll
                    for (int j = 0; j < 2; j++)
                        wmma::mma_sync(acc[i][j], fa[i], fb[j], acc[i][j]);
            } else {
                wmma::fragment<wmma::matrix_b, 16, 16, 16, bf16, wmma::col_major> fb[2];
#pragma unroll
                for (int j = 0; j < 2; j++)
                    wmma::load_matrix_sync(fb[j], &Bs[(wn * 32 + j * 16) * 48 + kk], 48);
#pragma unroll
                for (int i = 0; i < 4; i++)
#pragma unroll
                    for (int j = 0; j < 2; j++)
                        wmma::mma_sync(acc[i][j], fa[i], fb[j], acc[i][j]);
            }
        }
        __syncthreads();
    }

    // ---------------- epilogue ----------------
    float zsum = 0.f;
#pragma unroll
    for (int i = 0; i < 4; i++) {
#pragma unroll
        for (int j = 0; j < 2; j++) {
            wmma::store_matrix_sync(epi_buf[w], acc[i][j], 16, wmma::mem_row_major);
            __syncwarp();
            int gm = m0 + wm * 64 + i * 16;
            int gn = n0 + wn * 32 + j * 16;
            for (int e = lane; e < 256; e += 32) {
                int r = e >> 4, c = e & 15;
                float v = epi_buf[w][e];
                int mm = gm + r, nn = gn + c;
                if (EK == 0) {
                    v = (v + e0[nn]) * sigmoidf(e1[nn]) * 0.03125f;
                    g_qr[(size_t)mm * H + nn] = __float2bfloat16(v);
                } else if (EK == 1) {
                    float ev = expf(v);
                    bf16 eb = __float2bfloat16(ev);
                    g_E[(size_t)bz * SEQ * SEQ + (size_t)mm * SEQ + nn] = eb;
                    zsum += __bfloat162float(eb);
                } else {
                    size_t o = (size_t)bz * SEQ * H + (size_t)mm * H + nn;
                    outf[o] = v * g_Zinv[bz] + g_xqn_f32[o];
                }
            }
            __syncwarp();
        }
    }

    if (EK == 1) {
#pragma unroll
        for (int o = 16; o; o >>= 1) zsum += __shfl_xor_sync(0xffffffffu, zsum, o);
        if (lane == 0) red[w] = zsum;
        __syncthreads();
        if (tid == 0) {
            float t = 0.f;
#pragma unroll
            for (int i = 0; i < 8; i++) t += red[i];
            g_Zpart[(bz * gridDim.y + blockIdx.y) * gridDim.x + blockIdx.x] = t;
        }
    }
}

// deterministic fixed-order reduction of per-tile partial sums -> 1/Z per batch
__global__ void zreduce_kernel() {
    int b = blockIdx.x, tid = threadIdx.x;
    __shared__ float sh[256];
    sh[tid] = g_Zpart[b * 256 + tid];
    __syncthreads();
    for (int o = 128; o; o >>= 1) {
        if (tid < o) sh[tid] += sh[tid + o];
        __syncthreads();
    }
    if (tid == 0) g_Zinv[b] = 1.f / sh[0];
}

// ---------------- launch ----------------
extern "C" void kernel_launch(void* const* d_in, const int* in_sizes, int n_in,
                              void* d_out, int out_size) {
    const float* x       = (const float*)d_in[0];
    const float* qn_w    = (const float*)d_in[1];
    const float* qn_b    = (const float*)d_in[2];
    const float* kvn_w   = (const float*)d_in[3];
    const float* kvn_b   = (const float*)d_in[4];
    const float* q_prime = (const float*)d_in[5];
    const float* k_prime = (const float*)d_in[6];
    const float* v_prime = (const float*)d_in[7];
    const float* qW      = (const float*)d_in[8];
    const float* qb      = (const float*)d_in[9];
    const float* v1W     = (const float*)d_in[10];
    const float* v1b     = (const float*)d_in[11];
    const float* v2W     = (const float*)d_in[12];
    const float* v2b     = (const float*)d_in[13];
    float* out = (float*)d_out;

    cvt_qw_kernel<<<4096, 256>>>(qW);
    gate_kernel<<<128, 256>>>(v_prime, v1W, v1b, v2W, v2b);
    ln_kernel<<<ROWS, 256>>>(x, qn_w, qn_b, kvn_w, kvn_b, k_prime);

    // qr = (xqn @ qW^T + qb) * sigmoid(q') / 32
    gemm_kernel<0><<<dim3(H / 128, ROWS / 128, 1), 256>>>(qb, q_prime, nullptr);
    // E = exp(qr @ kr^T), per-tile partial sums
    gemm_kernel<1><<<dim3(SEQ / 128, SEQ / 128, BATCH), 256>>>(nullptr, nullptr, nullptr);
    // Zinv[b] = 1 / sum(E_b)
    zreduce_kernel<<<BATCH, 256>>>();
    // out = (E @ vr) * Zinv + xqn
    gemm_kernel<2><<<dim3(H / 128, SEQ / 128, BATCH), 256>>>(nullptr, nullptr, out);
}

// round 3
// speedup vs baseline: 3.5370x; 3.5370x over previous
#include <cuda_runtime.h>
#include <cuda_bf16.h>
#include <cstdint>

using bf16 = __nv_bfloat16;

#define H 1024
#define BATCH 8
#define SEQ 2048
#define ROWS (BATCH * SEQ)   // 16384

// ---- GEMM tile config (mma.sync path; tcgen05 unavailable: ptxas target is sm_103 base) ----
#define BM 128
#define BN 128
#define BK 64
#define NSTG 3
#define STG_BYTES (2 * BM * BK * 2)          // A(16KB)+B(16KB) = 32KB per stage
#define SMEM_BYTES (NSTG * STG_BYTES)        // 96KB

// ---------------- scratch (static device globals; no allocation) ----------------
__device__ float g_xqn_f32[(size_t)ROWS * H];          // 64 MB
__device__ bf16  g_xqn_bf [(size_t)ROWS * H];          // 32 MB
__device__ bf16  g_kr     [(size_t)ROWS * H];          // 32 MB
__device__ bf16  g_vr     [(size_t)ROWS * H];          // 32 MB
__device__ bf16  g_vrT    [(size_t)BATCH * H * SEQ];   // 32 MB
__device__ bf16  g_qr     [(size_t)ROWS * H];          // 32 MB (pre-scaled 1/32)
__device__ bf16  g_E      [(size_t)BATCH * SEQ * SEQ]; // 64 MB
__device__ bf16  g_qWb    [(size_t)H * H];             // 2 MB
__device__ float g_gate   [H];
__device__ float g_Zpart  [BATCH * 256];
__device__ float g_Zinv   [BATCH];

__device__ __forceinline__ float sigmoidf(float x) { return 1.f / (1.f + expf(-x)); }

__device__ __forceinline__ void store_bf4(bf16* p, float a, float b, float c, float d) {
    __nv_bfloat162 lo = __floats2bfloat162_rn(a, b);
    __nv_bfloat162 hi = __floats2bfloat162_rn(c, d);
    uint2 u;
    u.x = *reinterpret_cast<unsigned*>(&lo);
    u.y = *reinterpret_cast<unsigned*>(&hi);
    *reinterpret_cast<uint2*>(p) = u;
}

__device__ __forceinline__ uint32_t smem_u32(const void* p) {
    uint32_t a;
    asm("{ .reg .u64 t; cvta.to.shared.u64 t, %1; cvt.u32.u64 %0, t; }" : "=r"(a) : "l"(p));
    return a;
}

__device__ __forceinline__ void cp16(uint32_t dst, const void* src) {
    asm volatile("cp.async.cg.shared.global [%0], [%1], 16;" :: "r"(dst), "l"(src) : "memory");
}
#define CP_COMMIT() asm volatile("cp.async.commit_group;" ::: "memory")
#define CP_WAIT1()  asm volatile("cp.async.wait_group 1;" ::: "memory")

__device__ __forceinline__ void ldsm4(uint32_t* r, uint32_t a) {
    asm volatile("ldmatrix.sync.aligned.m8n8.x4.shared.b16 {%0,%1,%2,%3}, [%4];"
                 : "=r"(r[0]), "=r"(r[1]), "=r"(r[2]), "=r"(r[3]) : "r"(a));
}

__device__ __forceinline__ void mma16816(float* c, const uint32_t* a, uint32_t b0, uint32_t b1) {
    asm volatile(
        "mma.sync.aligned.m16n8k16.row.col.f32.bf16.bf16.f32 "
        "{%0,%1,%2,%3}, {%4,%5,%6,%7}, {%8,%9}, {%0,%1,%2,%3};"
        : "+f"(c[0]), "+f"(c[1]), "+f"(c[2]), "+f"(c[3])
        : "r"(a[0]), "r"(a[1]), "r"(a[2]), "r"(a[3]), "r"(b0), "r"(b1));
}

// ---------------- small prep kernels ----------------
__global__ void cvt_qw_kernel(const float* __restrict__ qW) {
    int i = blockIdx.x * blockDim.x + threadIdx.x;
    if (i < H * H) g_qWb[i] = __float2bfloat16(qW[i]);
}

__global__ void gate_kernel(const float* __restrict__ v_prime,
                            const float* __restrict__ v1W, const float* __restrict__ v1b,
                            const float* __restrict__ v2W, const float* __restrict__ v2b) {
    int warp = (blockIdx.x * blockDim.x + threadIdx.x) >> 5;
    int lane = threadIdx.x & 31;
    if (warp >= H) return;
    float s1 = 0.f, s2 = 0.f;
    for (int i = lane; i < H; i += 32) {
        float vp = sigmoidf(v_prime[i]);
        s1 += vp * v1W[warp * H + i];
        s2 += vp * v2W[warp * H + i];
    }
#pragma unroll
    for (int o = 16; o; o >>= 1) {
        s1 += __shfl_xor_sync(0xffffffffu, s1, o);
        s2 += __shfl_xor_sync(0xffffffffu, s2, o);
    }
    if (lane == 0)
        g_gate[warp] = sigmoidf(s1 + v1b[warp]) * tanhf(s2 + v2b[warp]);
}

// ---------------- fused dual LayerNorm + elementwise ----------------
__global__ void ln_kernel(const float* __restrict__ x,
                          const float* __restrict__ qn_w, const float* __restrict__ qn_b,
                          const float* __restrict__ kvn_w, const float* __restrict__ kvn_b,
                          const float* __restrict__ k_prime) {
    int row = blockIdx.x;
    int tid = threadIdx.x;
    size_t base = (size_t)row * H;
    float4 v = *reinterpret_cast<const float4*>(x + base + tid * 4);
    float s  = v.x + v.y + v.z + v.w;
    float ss = v.x * v.x + v.y * v.y + v.z * v.z + v.w * v.w;
#pragma unroll
    for (int o = 16; o; o >>= 1) {
        s  += __shfl_xor_sync(0xffffffffu, s, o);
        ss += __shfl_xor_sync(0xffffffffu, ss, o);
    }
    __shared__ float shs[8], shss[8];
    int w = tid >> 5, l = tid & 31;
    if (l == 0) { shs[w] = s; shss[w] = ss; }
    __syncthreads();
    float ts = 0.f, tss = 0.f;
#pragma unroll
    for (int i = 0; i < 8; i++) { ts += shs[i]; tss += shss[i]; }
    float mean = ts * (1.f / H);
    float var  = tss * (1.f / H) - mean * mean;
    float rstd = rsqrtf(var + 1e-5f);

    int j = tid * 4;
    float4 qw  = *reinterpret_cast<const float4*>(qn_w + j);
    float4 qb4 = *reinterpret_cast<const float4*>(qn_b + j);
    float4 kw  = *reinterpret_cast<const float4*>(kvn_w + j);
    float4 kb4 = *reinterpret_cast<const float4*>(kvn_b + j);
    float4 kp  = *reinterpret_cast<const float4*>(k_prime + j);
    float4 gt  = *reinterpret_cast<const float4*>(g_gate + j);

    float xh0 = (v.x - mean) * rstd, xh1 = (v.y - mean) * rstd;
    float xh2 = (v.z - mean) * rstd, xh3 = (v.w - mean) * rstd;

    float xq0 = xh0 * qw.x + qb4.x, xq1 = xh1 * qw.y + qb4.y;
    float xq2 = xh2 * qw.z + qb4.z, xq3 = xh3 * qw.w + qb4.w;
    float xk0 = xh0 * kw.x + kb4.x, xk1 = xh1 * kw.y + kb4.y;
    float xk2 = xh2 * kw.z + kb4.z, xk3 = xh3 * kw.w + kb4.w;

    *reinterpret_cast<float4*>(g_xqn_f32 + base + j) = make_float4(xq0, xq1, xq2, xq3);
    store_bf4(g_xqn_bf + base + j, xq0, xq1, xq2, xq3);
    store_bf4(g_kr + base + j, xk0 * sigmoidf(kp.x), xk1 * sigmoidf(kp.y),
                               xk2 * sigmoidf(kp.z), xk3 * sigmoidf(kp.w));
    store_bf4(g_vr + base + j, xk0 * gt.x, xk1 * gt.y, xk2 * gt.z, xk3 * gt.w);
}

// ---------------- vr transpose: [b, s, h] -> [b, h, s] ----------------
__global__ void transpose_vr_kernel() {
    __shared__ bf16 t[32][33];
    int b  = blockIdx.z;
    int h0 = blockIdx.x * 32, s0 = blockIdx.y * 32;
    const bf16* src = g_vr  + (size_t)b * SEQ * H;
    bf16*       dst = g_vrT + (size_t)b * H * SEQ;
    int tx = threadIdx.x, ty = threadIdx.y;
#pragma unroll
    for (int j = 0; j < 32; j += 8)
        t[ty + j][tx] = src[(size_t)(s0 + ty + j) * H + h0 + tx];
    __syncthreads();
#pragma unroll
    for (int j = 0; j < 32; j += 8)
        dst[(size_t)(h0 + ty + j) * SEQ + s0 + tx] = t[tx][ty + j];
}

// ---------------- pipelined mma.sync GEMM: C = A[M,K] * B[N,K]^T ----------------
// EK = 0: qr  = (xqn_bf @ qWb^T + qb) * sigmoid(q') / 32     -> g_qr (bf16)
// EK = 1: E   = exp(qr @ kr^T)                                -> g_E (bf16) + tile Z partials
// EK = 2: out = (E @ vrT^T) * Zinv[b] + xqn_f32               -> d_out (fp32)
template<int EK>
__global__ void __launch_bounds__(256, 2)
gemm_mma(const float* __restrict__ e0, const float* __restrict__ e1,
         float* __restrict__ outf) {
    constexpr int Kdim = (EK == 2) ? 2048 : 1024;
    constexpr int LDA  = (EK == 2) ? 2048 : 1024;
    constexpr int LDB  = (EK == 2) ? 2048 : 1024;
    constexpr int KT   = Kdim / BK;

    extern __shared__ char smem[];
    uint32_t sm = smem_u32(smem);

    int tid  = threadIdx.x;
    int lane = tid & 31, w = tid >> 5;
    int wm = w >> 2, wn = w & 3;              // warp grid 2 (m) x 4 (n); warp tile 64x32
    int bz = blockIdx.z;
    int m0 = blockIdx.y * BM, n0 = blockIdx.x * BN;

    const bf16 *A, *B;
    if (EK == 0)      { A = g_xqn_bf;                       B = g_qWb; }
    else if (EK == 1) { A = g_qr  + (size_t)bz * SEQ * H;   B = g_kr  + (size_t)bz * SEQ * H; }
    else              { A = g_E   + (size_t)bz * SEQ * SEQ; B = g_vrT + (size_t)bz * H * SEQ; }

    // ---- load geometry: 128 rows x 64 cols bf16, 8 chunks of 16B per row, XOR swizzle ----
    int lr = tid >> 3;                         // 0..31 (base row, stride 32)
    int lc = tid & 7;                          // chunk
    uint32_t lsw = (uint32_t)((lc ^ (lr & 7)) << 4);
    const char* Ag = (const char*)(A + (size_t)(m0 + lr) * LDA) + lc * 16;
    const char* Bg = (const char*)(B + (size_t)(n0 + lr) * LDB) + lc * 16;

    auto load_tile = [&](int s, int ktile) {
        uint32_t base = sm + s * STG_BYTES;
        const char* ag = Ag + (size_t)ktile * (BK * 2);
        const char* bg = Bg + (size_t)ktile * (BK * 2);
#pragma unroll
        for (int i = 0; i < 4; i++)
            cp16(base + (uint32_t)(lr + i * 32) * 128 + lsw, ag + (size_t)i * 32 * LDA * 2);
#pragma unroll
        for (int i = 0; i < 4; i++)
            cp16(base + 16384u + (uint32_t)(lr + i * 32) * 128 + lsw, bg + (size_t)i * 32 * LDB * 2);
    };

    load_tile(0, 0); CP_COMMIT();
    load_tile(1, 1); CP_COMMIT();

    float acc[4][4][4];
#pragma unroll
    for (int i = 0; i < 4; i++)
#pragma unroll
        for (int j = 0; j < 4; j++)
#pragma unroll
            for (int q = 0; q < 4; q++) acc[i][j][q] = 0.f;

    int rlA = wm * 64 + (lane & 15);           // ldmatrix row within tile (A)
    int rlB = wn * 32 + (lane & 15);           // (B)
    int hi  = lane >> 4;                       // 0/1 -> +8 k-chunk

    for (int kt = 0; kt < KT; kt++) {
        CP_WAIT1();
        __syncthreads();
        int s = kt % NSTG;
        uint32_t sA = sm + s * STG_BYTES;
        uint32_t sB = sA + 16384u;

        int nt = kt + NSTG - 1;
        if (nt < KT) load_tile(nt % NSTG, nt);
        CP_COMMIT();

#pragma unroll
        for (int ks = 0; ks < 4; ks++) {
            int chunk = ks * 2 + hi;
            uint32_t ar[4][4], br[2][4];
#pragma unroll
            for (int mi = 0; mi < 4; mi++) {
                int r = rlA + mi * 16;
                ldsm4(ar[mi], sA + (uint32_t)r * 128 + (uint32_t)((chunk ^ (r & 7)) << 4));
            }
#pragma unroll
            for (int nj = 0; nj < 2; nj++) {
                int r = rlB + nj * 16;
                ldsm4(br[nj], sB + (uint32_t)r * 128 + (uint32_t)((chunk ^ (r & 7)) << 4));
            }
            // n8 fragments: {br[nj][0], br[nj][2]} = n 0-7, {br[nj][1], br[nj][3]} = n 8-15
#pragma unroll
            for (int mi = 0; mi < 4; mi++) {
                mma16816(acc[mi][0], ar[mi], br[0][0], br[0][2]);
                mma16816(acc[mi][1], ar[mi], br[0][1], br[0][3]);
                mma16816(acc[mi][2], ar[mi], br[1][0], br[1][2]);
                mma16816(acc[mi][3], ar[mi], br[1][1], br[1][3]);
            }
        }
        __syncthreads();
    }

    // ---------------- register epilogue ----------------
    float zs = 0.f;
    float zi = (EK == 2) ? g_Zinv[bz] : 0.f;

#pragma unroll
    for (int ni = 0; ni < 4; ni++) {
        int col = n0 + wn * 32 + ni * 8 + (lane & 3) * 2;
        float b0 = 0.f, b1 = 0.f, p0 = 0.f, p1 = 0.f;
        if (EK == 0) {
            b0 = e0[col]; b1 = e0[col + 1];
            p0 = sigmoidf(e1[col]) * 0.03125f;
            p1 = sigmoidf(e1[col + 1]) * 0.03125f;
        }
#pragma unroll
        for (int mi = 0; mi < 4; mi++) {
            int r0 = m0 + wm * 64 + mi * 16 + (lane >> 2);
            int r1 = r0 + 8;
            float* c = acc[mi][ni];
            if (EK == 0) {
                __nv_bfloat162 u0 = __floats2bfloat162_rn((c[0] + b0) * p0, (c[1] + b1) * p1);
                __nv_bfloat162 u1 = __floats2bfloat162_rn((c[2] + b0) * p0, (c[3] + b1) * p1);
                *reinterpret_cast<__nv_bfloat162*>(g_qr + (size_t)r0 * H + col) = u0;
                *reinterpret_cast<__nv_bfloat162*>(g_qr + (size_t)r1 * H + col) = u1;
            } else if (EK == 1) {
                __nv_bfloat162 u0 = __floats2bfloat162_rn(expf(c[0]), expf(c[1]));
                __nv_bfloat162 u1 = __floats2bfloat162_rn(expf(c[2]), expf(c[3]));
                zs += __bfloat162float(u0.x) + __bfloat162float(u0.y)
                    + __bfloat162float(u1.x) + __bfloat162float(u1.y);
                size_t bb = (size_t)bz * SEQ * SEQ;
                *reinterpret_cast<__nv_bfloat162*>(g_E + bb + (size_t)r0 * SEQ + col) = u0;
                *reinterpret_cast<__nv_bfloat162*>(g_E + bb + (size_t)r1 * SEQ + col) = u1;
            } else {
                size_t o0 = ((size_t)bz * SEQ + r0) * H + col;
                size_t o1 = ((size_t)bz * SEQ + r1) * H + col;
                float2 x0 = *reinterpret_cast<const float2*>(g_xqn_f32 + o0);
                float2 x1 = *reinterpret_cast<const float2*>(g_xqn_f32 + o1);
                float2 y0 = make_float2(c[0] * zi + x0.x, c[1] * zi + x0.y);
                float2 y1 = make_float2(c[2] * zi + x1.x, c[3] * zi + x1.y);
                *reinterpret_cast<float2*>(outf + o0) = y0;
                *reinterpret_cast<float2*>(outf + o1) = y1;
            }
        }
    }

    if (EK == 1) {
        __shared__ float red[8];
#pragma unroll
        for (int o = 16; o; o >>= 1) zs += __shfl_xor_sync(0xffffffffu, zs, o);
        if (lane == 0) red[w] = zs;
        __syncthreads();
        if (tid == 0) {
            float t = 0.f;
#pragma unroll
            for (int i = 0; i < 8; i++) t += red[i];
            g_Zpart[bz * 256 + blockIdx.y * gridDim.x + blockIdx.x] = t;
        }
    }
}

// deterministic fixed-order reduction -> 1/Z per batch
__global__ void zreduce_kernel() {
    int b = blockIdx.x, tid = threadIdx.x;
    __shared__ float sh[256];
    sh[tid] = g_Zpart[b * 256 + tid];
    __syncthreads();
    for (int o = 128; o; o >>= 1) {
        if (tid < o) sh[tid] += sh[tid + o];
        __syncthreads();
    }
    if (tid == 0) g_Zinv[b] = 1.f / sh[0];
}

// ---------------- launch ----------------
extern "C" void kernel_launch(void* const* d_in, const int* in_sizes, int n_in,
                              void* d_out, int out_size) {
    const float* x       = (const float*)d_in[0];
    const float* qn_w    = (const float*)d_in[1];
    const float* qn_b    = (const float*)d_in[2];
    const float* kvn_w   = (const float*)d_in[3];
    const float* kvn_b   = (const float*)d_in[4];
    const float* q_prime = (const float*)d_in[5];
    const float* k_prime = (const float*)d_in[6];
    const float* v_prime = (const float*)d_in[7];
    const float* qW      = (const float*)d_in[8];
    const float* qb      = (const float*)d_in[9];
    const float* v1W     = (const float*)d_in[10];
    const float* v1b     = (const float*)d_in[11];
    const float* v2W     = (const float*)d_in[12];
    const float* v2b     = (const float*)d_in[13];
    float* out = (float*)d_out;

    static int inited = 0;
    if (!inited) {
        cudaFuncSetAttribute(gemm_mma<0>, cudaFuncAttributeMaxDynamicSharedMemorySize, SMEM_BYTES);
        cudaFuncSetAttribute(gemm_mma<1>, cudaFuncAttributeMaxDynamicSharedMemorySize, SMEM_BYTES);
        cudaFuncSetAttribute(gemm_mma<2>, cudaFuncAttributeMaxDynamicSharedMemorySize, SMEM_BYTES);
        inited = 1;
    }

    cvt_qw_kernel<<<4096, 256>>>(qW);
    gate_kernel<<<128, 256>>>(v_prime, v1W, v1b, v2W, v2b);
    ln_kernel<<<ROWS, 256>>>(x, qn_w, qn_b, kvn_w, kvn_b, k_prime);
    transpose_vr_kernel<<<dim3(H / 32, SEQ / 32, BATCH), dim3(32, 8)>>>();

    // qr = (xqn @ qW^T + qb) * sigmoid(q') / 32
    gemm_mma<0><<<dim3(H / BN, ROWS / BM, 1), 256, SMEM_BYTES>>>(qb, q_prime, nullptr);
    // E = exp(qr @ kr^T) + tile partial sums
    gemm_mma<1><<<dim3(SEQ / BN, SEQ / BM, BATCH), 256, SMEM_BYTES>>>(nullptr, nullptr, nullptr);
    // Zinv[b] = 1 / sum(E_b)
    zreduce_kernel<<<BATCH, 256>>>();
    // out = (E @ vrT^T) * Zinv + xqn
    gemm_mma<2><<<dim3(H / BN, SEQ / BM, BATCH), 256, SMEM_BYTES>>>(nullptr, nullptr, out);
}

// round 4
// speedup vs baseline: 3.6601x; 1.0348x over previous
#include <cuda_runtime.h>
#include <cuda_bf16.h>
#include <cstdint>

using bf16 = __nv_bfloat16;

#define H 1024
#define BATCH 8
#define SEQ 2048
#define ROWS (BATCH * SEQ)   // 16384

// ---- GEMM tile config: 128x128x64, 4 warps (2x2), warp tile 64x64 ----
#define BM 128
#define BN 128
#define BK 64
#define NSTG 3
#define STG_BYTES (2 * BM * BK * 2)          // A(16KB)+B(16KB) = 32KB per stage
#define SMEM_BYTES (NSTG * STG_BYTES)        // 96KB -> 2 CTAs/SM

// ---------------- scratch (static device globals; no allocation) ----------------
__device__ float g_xqn_f32[(size_t)ROWS * H];          // 64 MB
__device__ bf16  g_xqn_bf [(size_t)ROWS * H];          // 32 MB
__device__ bf16  g_kr     [(size_t)ROWS * H];          // 32 MB
__device__ bf16  g_vr     [(size_t)ROWS * H];          // 32 MB
__device__ bf16  g_qr     [(size_t)ROWS * H];          // 32 MB (pre-scaled 1/32)
__device__ bf16  g_E      [(size_t)BATCH * SEQ * SEQ]; // 64 MB
__device__ bf16  g_qWb    [(size_t)H * H];             // 2 MB
__device__ float g_gate   [H];
__device__ float g_Zpart  [BATCH * 256];
__device__ float g_Zinv   [BATCH];

__device__ __forceinline__ float sigmoidf(float x) { return 1.f / (1.f + expf(-x)); }

__device__ __forceinline__ void store_bf4(bf16* p, float a, float b, float c, float d) {
    __nv_bfloat162 lo = __floats2bfloat162_rn(a, b);
    __nv_bfloat162 hi = __floats2bfloat162_rn(c, d);
    uint2 u;
    u.x = *reinterpret_cast<unsigned*>(&lo);
    u.y = *reinterpret_cast<unsigned*>(&hi);
    *reinterpret_cast<uint2*>(p) = u;
}

__device__ __forceinline__ uint32_t smem_u32(const void* p) {
    uint32_t a;
    asm("{ .reg .u64 t; cvta.to.shared.u64 t, %1; cvt.u32.u64 %0, t; }" : "=r"(a) : "l"(p));
    return a;
}

__device__ __forceinline__ void cp16(uint32_t dst, const void* src) {
    asm volatile("cp.async.cg.shared.global [%0], [%1], 16;" :: "r"(dst), "l"(src) : "memory");
}
#define CP_COMMIT() asm volatile("cp.async.commit_group;" ::: "memory")
#define CP_WAIT1()  asm volatile("cp.async.wait_group 1;" ::: "memory")

__device__ __forceinline__ void ldsm4(uint32_t* r, uint32_t a) {
    asm volatile("ldmatrix.sync.aligned.m8n8.x4.shared.b16 {%0,%1,%2,%3}, [%4];"
                 : "=r"(r[0]), "=r"(r[1]), "=r"(r[2]), "=r"(r[3]) : "r"(a));
}
__device__ __forceinline__ void ldsm4t(uint32_t* r, uint32_t a) {
    asm volatile("ldmatrix.sync.aligned.m8n8.x4.trans.shared.b16 {%0,%1,%2,%3}, [%4];"
                 : "=r"(r[0]), "=r"(r[1]), "=r"(r[2]), "=r"(r[3]) : "r"(a));
}

__device__ __forceinline__ void mma16816(float* c, const uint32_t* a, uint32_t b0, uint32_t b1) {
    asm volatile(
        "mma.sync.aligned.m16n8k16.row.col.f32.bf16.bf16.f32 "
        "{%0,%1,%2,%3}, {%4,%5,%6,%7}, {%8,%9}, {%0,%1,%2,%3};"
        : "+f"(c[0]), "+f"(c[1]), "+f"(c[2]), "+f"(c[3])
        : "r"(a[0]), "r"(a[1]), "r"(a[2]), "r"(a[3]), "r"(b0), "r"(b1));
}

// ---------------- small prep kernels ----------------
__global__ void cvt_qw_kernel(const float* __restrict__ qW) {
    int i = blockIdx.x * blockDim.x + threadIdx.x;
    if (i < H * H) g_qWb[i] = __float2bfloat16(qW[i]);
}

__global__ void gate_kernel(const float* __restrict__ v_prime,
                            const float* __restrict__ v1W, const float* __restrict__ v1b,
                            const float* __restrict__ v2W, const float* __restrict__ v2b) {
    int warp = (blockIdx.x * blockDim.x + threadIdx.x) >> 5;
    int lane = threadIdx.x & 31;
    if (warp >= H) return;
    float s1 = 0.f, s2 = 0.f;
    for (int i = lane; i < H; i += 32) {
        float vp = sigmoidf(v_prime[i]);
        s1 += vp * v1W[warp * H + i];
        s2 += vp * v2W[warp * H + i];
    }
#pragma unroll
    for (int o = 16; o; o >>= 1) {
        s1 += __shfl_xor_sync(0xffffffffu, s1, o);
        s2 += __shfl_xor_sync(0xffffffffu, s2, o);
    }
    if (lane == 0)
        g_gate[warp] = sigmoidf(s1 + v1b[warp]) * tanhf(s2 + v2b[warp]);
}

// ---------------- fused dual LayerNorm + elementwise ----------------
__global__ void ln_kernel(const float* __restrict__ x,
                          const float* __restrict__ qn_w, const float* __restrict__ qn_b,
                          const float* __restrict__ kvn_w, const float* __restrict__ kvn_b,
                          const float* __restrict__ k_prime) {
    int row = blockIdx.x;
    int tid = threadIdx.x;
    size_t base = (size_t)row * H;
    float4 v = *reinterpret_cast<const float4*>(x + base + tid * 4);
    float s  = v.x + v.y + v.z + v.w;
    float ss = v.x * v.x + v.y * v.y + v.z * v.z + v.w * v.w;
#pragma unroll
    for (int o = 16; o; o >>= 1) {
        s  += __shfl_xor_sync(0xffffffffu, s, o);
        ss += __shfl_xor_sync(0xffffffffu, ss, o);
    }
    __shared__ float shs[8], shss[8];
    int w = tid >> 5, l = tid & 31;
    if (l == 0) { shs[w] = s; shss[w] = ss; }
    __syncthreads();
    float ts = 0.f, tss = 0.f;
#pragma unroll
    for (int i = 0; i < 8; i++) { ts += shs[i]; tss += shss[i]; }
    float mean = ts * (1.f / H);
    float var  = tss * (1.f / H) - mean * mean;
    float rstd = rsqrtf(var + 1e-5f);

    int j = tid * 4;
    float4 qw  = *reinterpret_cast<const float4*>(qn_w + j);
    float4 qb4 = *reinterpret_cast<const float4*>(qn_b + j);
    float4 kw  = *reinterpret_cast<const float4*>(kvn_w + j);
    float4 kb4 = *reinterpret_cast<const float4*>(kvn_b + j);
    float4 kp  = *reinterpret_cast<const float4*>(k_prime + j);
    float4 gt  = *reinterpret_cast<const float4*>(g_gate + j);

    float xh0 = (v.x - mean) * rstd, xh1 = (v.y - mean) * rstd;
    float xh2 = (v.z - mean) * rstd, xh3 = (v.w - mean) * rstd;

    float xq0 = xh0 * qw.x + qb4.x, xq1 = xh1 * qw.y + qb4.y;
    float xq2 = xh2 * qw.z + qb4.z, xq3 = xh3 * qw.w + qb4.w;
    float xk0 = xh0 * kw.x + kb4.x, xk1 = xh1 * kw.y + kb4.y;
    float xk2 = xh2 * kw.z + kb4.z, xk3 = xh3 * kw.w + kb4.w;

    *reinterpret_cast<float4*>(g_xqn_f32 + base + j) = make_float4(xq0, xq1, xq2, xq3);
    store_bf4(g_xqn_bf + base + j, xq0, xq1, xq2, xq3);
    store_bf4(g_kr + base + j, xk0 * sigmoidf(kp.x), xk1 * sigmoidf(kp.y),
                               xk2 * sigmoidf(kp.z), xk3 * sigmoidf(kp.w));
    store_bf4(g_vr + base + j, xk0 * gt.x, xk1 * gt.y, xk2 * gt.z, xk3 * gt.w);
}

// ---------------- pipelined mma.sync GEMM ----------------
// EK = 0: qr  = (xqn_bf @ qWb^T + qb) * sigmoid(q') / 32   [B:(N,K)]   -> g_qr
// EK = 1: E   = exp(qr @ kr^T)                              [B:(N,K)]   -> g_E + Z partials
// EK = 2: out = (E @ vr) * Zinv[b] + xqn_f32                [B:(K,N)]   -> d_out
template<int EK>
__global__ void __launch_bounds__(128, 2)
gemm_mma(const float* __restrict__ e0, const float* __restrict__ e1,
         float* __restrict__ outf) {
    constexpr bool TRB = (EK == 2);           // B stored [K,N] row-major -> ldmatrix.trans
    constexpr int Kdim = (EK == 2) ? 2048 : 1024;
    constexpr int LDA  = (EK == 2) ? 2048 : 1024;
    constexpr int LDB  = 1024;                // qWb/kr: [N,1024]; vr: [K,1024]
    constexpr int KT   = Kdim / BK;

    extern __shared__ char smem[];
    uint32_t sm = smem_u32(smem);

    int tid  = threadIdx.x;
    int lane = tid & 31, w = tid >> 5;
    int wm = w >> 1, wn = w & 1;              // 2x2 warp grid, 64x64 warp tiles
    int bz = blockIdx.z;
    int m0 = blockIdx.y * BM, n0 = blockIdx.x * BN;

    const bf16 *A, *B;
    if (EK == 0)      { A = g_xqn_bf;                       B = g_qWb; }
    else if (EK == 1) { A = g_qr + (size_t)bz * SEQ * H;    B = g_kr + (size_t)bz * SEQ * H; }
    else              { A = g_E  + (size_t)bz * SEQ * SEQ;  B = g_vr + (size_t)bz * SEQ * H; }

    // ---- A loader geometry (128 rows x 64 cols, pitch 128B, 8 chunks/row) ----
    int ar_ = tid >> 3, ac_ = tid & 7;                      // row 0..15 (+i*16), chunk
    uint32_t aswz = (uint32_t)((ac_ ^ (ar_ & 7)) << 4);
    const char* Ag = (const char*)(A + (size_t)(m0 + ar_) * LDA) + ac_ * 16;

    // ---- B loader geometry ----
    // TRB: [64 k-rows x 128 n-cols], pitch 256B, 16 chunks/row
    // else: [128 n-rows x 64 k-cols], pitch 128B, 8 chunks/row (same as A)
    int br_, bc_;
    uint32_t bswz;
    const char* Bg;
    if (TRB) {
        br_ = tid >> 4; bc_ = tid & 15;                     // row 0..7 (+i*8), chunk 0..15
        bswz = (uint32_t)((((bc_ & 7) ^ (br_ & 7)) | (bc_ & 8)) << 4);
        Bg = (const char*)(B + (size_t)br_ * LDB + n0 + bc_ * 8);
    } else {
        br_ = ar_; bc_ = ac_;
        bswz = aswz;
        Bg = (const char*)(B + (size_t)(n0 + br_) * LDB) + bc_ * 16;
    }

    auto load_tile = [&](int s, int kt) {
        uint32_t base = sm + s * STG_BYTES;
        const char* ag = Ag + (size_t)kt * (BK * 2);
#pragma unroll
        for (int i = 0; i < 8; i++)
            cp16(base + (uint32_t)(ar_ + i * 16) * 128 + aswz, ag + (size_t)i * 16 * LDA * 2);
        uint32_t bb = base + 16384u;
        if (TRB) {
            const char* bg = Bg + (size_t)kt * BK * LDB * 2;
#pragma unroll
            for (int i = 0; i < 8; i++)
                cp16(bb + (uint32_t)(br_ + i * 8) * 256 + bswz, bg + (size_t)i * 8 * LDB * 2);
        } else {
            const char* bg = Bg + (size_t)kt * (BK * 2);
#pragma unroll
            for (int i = 0; i < 8; i++)
                cp16(bb + (uint32_t)(br_ + i * 16) * 128 + bswz, bg + (size_t)i * 16 * LDB * 2);
        }
    };

    load_tile(0, 0); CP_COMMIT();
    load_tile(1, 1); CP_COMMIT();

    float acc[4][8][4];
#pragma unroll
    for (int i = 0; i < 4; i++)
#pragma unroll
        for (int j = 0; j < 8; j++)
#pragma unroll
            for (int q = 0; q < 4; q++) acc[i][j][q] = 0.f;

    int rlA = wm * 64 + (lane & 15);
    int hi  = lane >> 4;
    int rlB = wn * 64 + (lane & 15);                        // non-trans B rows
    int tK  = lane & 15;                                    // trans B: k-row within k16
    int tN  = wn * 8 + (lane >> 4);                         // trans B: chunk base (n/8)

    for (int kt = 0; kt < KT; kt++) {
        CP_WAIT1();
        __syncthreads();
        int s = kt % NSTG;
        uint32_t sA = sm + s * STG_BYTES;
        uint32_t sB = sA + 16384u;

        int nt = kt + NSTG - 1;
        if (nt < KT) load_tile(nt % NSTG, nt);
        CP_COMMIT();

#pragma unroll
        for (int ks = 0; ks < 4; ks++) {
            uint32_t arf[4][4], brf[4][4];
            int chunk = ks * 2 + hi;
#pragma unroll
            for (int mi = 0; mi < 4; mi++) {
                int r = rlA + mi * 16;
                ldsm4(arf[mi], sA + (uint32_t)r * 128 + (uint32_t)((chunk ^ (r & 7)) << 4));
            }
            if (TRB) {
                int r = ks * 16 + tK;
#pragma unroll
                for (int nj = 0; nj < 4; nj++) {
                    int cn = tN + nj * 2;
                    uint32_t phys = (uint32_t)((((cn & 7) ^ (r & 7)) | (cn & 8)) << 4);
                    ldsm4t(brf[nj], sB + (uint32_t)r * 256 + phys);
                }
#pragma unroll
                for (int mi = 0; mi < 4; mi++)
#pragma unroll
                    for (int nj = 0; nj < 4; nj++) {
                        mma16816(acc[mi][nj * 2 + 0], arf[mi], brf[nj][0], brf[nj][1]);
                        mma16816(acc[mi][nj * 2 + 1], arf[mi], brf[nj][2], brf[nj][3]);
                    }
            } else {
#pragma unroll
                for (int nj = 0; nj < 4; nj++) {
                    int r = rlB + nj * 16;
                    ldsm4(brf[nj], sB + (uint32_t)r * 128 + (uint32_t)((chunk ^ (r & 7)) << 4));
                }
#pragma unroll
                for (int mi = 0; mi < 4; mi++)
#pragma unroll
                    for (int nj = 0; nj < 4; nj++) {
                        mma16816(acc[mi][nj * 2 + 0], arf[mi], brf[nj][0], brf[nj][2]);
                        mma16816(acc[mi][nj * 2 + 1], arf[mi], brf[nj][1], brf[nj][3]);
                    }
            }
        }
    }

    // ---------------- register epilogue ----------------
    float zs = 0.f;
    float zi = (EK == 2) ? g_Zinv[bz] : 0.f;

#pragma unroll
    for (int nj = 0; nj < 8; nj++) {
        int col = n0 + wn * 64 + nj * 8 + (lane & 3) * 2;
        float b0 = 0.f, b1 = 0.f, p0 = 0.f, p1 = 0.f;
        if (EK == 0) {
            float2 bb = *reinterpret_cast<const float2*>(e0 + col);
            float2 pp = *reinterpret_cast<const float2*>(e1 + col);
            b0 = bb.x; b1 = bb.y;
            p0 = sigmoidf(pp.x) * 0.03125f;
            p1 = sigmoidf(pp.y) * 0.03125f;
        }
#pragma unroll
        for (int mi = 0; mi < 4; mi++) {
            int r0 = m0 + wm * 64 + mi * 16 + (lane >> 2);
            int r1 = r0 + 8;
            float* c = acc[mi][nj];
            if (EK == 0) {
                __nv_bfloat162 u0 = __floats2bfloat162_rn((c[0] + b0) * p0, (c[1] + b1) * p1);
                __nv_bfloat162 u1 = __floats2bfloat162_rn((c[2] + b0) * p0, (c[3] + b1) * p1);
                *reinterpret_cast<__nv_bfloat162*>(g_qr + (size_t)r0 * H + col) = u0;
                *reinterpret_cast<__nv_bfloat162*>(g_qr + (size_t)r1 * H + col) = u1;
            } else if (EK == 1) {
                __nv_bfloat162 u0 = __floats2bfloat162_rn(expf(c[0]), expf(c[1]));
                __nv_bfloat162 u1 = __floats2bfloat162_rn(expf(c[2]), expf(c[3]));
                zs += __bfloat162float(u0.x) + __bfloat162float(u0.y)
                    + __bfloat162float(u1.x) + __bfloat162float(u1.y);
                size_t bb = (size_t)bz * SEQ * SEQ;
                *reinterpret_cast<__nv_bfloat162*>(g_E + bb + (size_t)r0 * SEQ + col) = u0;
                *reinterpret_cast<__nv_bfloat162*>(g_E + bb + (size_t)r1 * SEQ + col) = u1;
            } else {
                size_t o0 = ((size_t)bz * SEQ + r0) * H + col;
                size_t o1 = ((size_t)bz * SEQ + r1) * H + col;
                float2 x0 = *reinterpret_cast<const float2*>(g_xqn_f32 + o0);
                float2 x1 = *reinterpret_cast<const float2*>(g_xqn_f32 + o1);
                *reinterpret_cast<float2*>(outf + o0) =
                    make_float2(c[0] * zi + x0.x, c[1] * zi + x0.y);
                *reinterpret_cast<float2*>(outf + o1) =
                    make_float2(c[2] * zi + x1.x, c[3] * zi + x1.y);
            }
        }
    }

    if (EK == 1) {
        __shared__ float red[4];
#pragma unroll
        for (int o = 16; o; o >>= 1) zs += __shfl_xor_sync(0xffffffffu, zs, o);
        if (lane == 0) red[w] = zs;
        __syncthreads();
        if (tid == 0)
            g_Zpart[bz * 256 + blockIdx.y * gridDim.x + blockIdx.x] =
                red[0] + red[1] + red[2] + red[3];
    }
}

// deterministic fixed-order reduction -> 1/Z per batch
__global__ void zreduce_kernel() {
    int b = blockIdx.x, tid = threadIdx.x;
    __shared__ float sh[256];
    sh[tid] = g_Zpart[b * 256 + tid];
    __syncthreads();
    for (int o = 128; o; o >>= 1) {
        if (tid < o) sh[tid] += sh[tid + o];
        __syncthreads();
    }
    if (tid == 0) g_Zinv[b] = 1.f / sh[0];
}

// ---------------- launch ----------------
extern "C" void kernel_launch(void* const* d_in, const int* in_sizes, int n_in,
                              void* d_out, int out_size) {
    const float* x       = (const float*)d_in[0];
    const float* qn_w    = (const float*)d_in[1];
    const float* qn_b    = (const float*)d_in[2];
    const float* kvn_w   = (const float*)d_in[3];
    const float* kvn_b   = (const float*)d_in[4];
    const float* q_prime = (const float*)d_in[5];
    const float* k_prime = (const float*)d_in[6];
    const float* v_prime = (const float*)d_in[7];
    const float* qW      = (const float*)d_in[8];
    const float* qb      = (const float*)d_in[9];
    const float* v1W     = (const float*)d_in[10];
    const float* v1b     = (const float*)d_in[11];
    const float* v2W     = (const float*)d_in[12];
    const float* v2b     = (const float*)d_in[13];
    float* out = (float*)d_out;

    static int inited = 0;
    if (!inited) {
        cudaFuncSetAttribute(gemm_mma<0>, cudaFuncAttributeMaxDynamicSharedMemorySize, SMEM_BYTES);
        cudaFuncSetAttribute(gemm_mma<1>, cudaFuncAttributeMaxDynamicSharedMemorySize, SMEM_BYTES);
        cudaFuncSetAttribute(gemm_mma<2>, cudaFuncAttributeMaxDynamicSharedMemorySize, SMEM_BYTES);
        inited = 1;
    }

    cvt_qw_kernel<<<4096, 256>>>(qW);
    gate_kernel<<<128, 256>>>(v_prime, v1W, v1b, v2W, v2b);
    ln_kernel<<<ROWS, 256>>>(x, qn_w, qn_b, kvn_w, kvn_b, k_prime);

    // qr = (xqn @ qW^T + qb) * sigmoid(q') / 32
    gemm_mma<0><<<dim3(H / BN, ROWS / BM, 1), 128, SMEM_BYTES>>>(qb, q_prime, nullptr);
    // E = exp(qr @ kr^T) + tile partial sums
    gemm_mma<1><<<dim3(SEQ / BN, SEQ / BM, BATCH), 128, SMEM_BYTES>>>(nullptr, nullptr, nullptr);
    // Zinv[b] = 1 / sum(E_b)
    zreduce_kernel<<<BATCH, 256>>>();
    // out = (E @ vr) * Zinv + xqn
    gemm_mma<2><<<dim3(H / BN, SEQ / BM, BATCH), 128, SMEM_BYTES>>>(nullptr, nullptr, out);
}